// round 16
// baseline (speedup 1.0000x reference)
#include <cuda_runtime.h>
#include <cuda_fp16.h>
#include <cstdint>

typedef unsigned long long u64;

#define CIN   32
#define COUT  32
#define HH    192
#define WW    192
#define NB    16
#define HWP   (HH * WW)          // 36864
#define NPIX  (NB * HWP)
#define NTAP  81

// NHWC fp16 copy of input: [n][y][x][ci], 64B per pixel
__device__ __align__(16) __half g_xh[(size_t)NPIX * CIN];
// B fragments, packed per ntile: [tap][ntile 4][lane 32] uint4 {B0lo,B0hi,B1lo,B1hi}
__device__ __align__(16) uint4 g_wf[NTAP * 4 * 32];

// ---------------------------------------------------------------------------
// Prep 1: Gaussian kernels -> B fragments (one thread per (co, ci))
// ---------------------------------------------------------------------------
__global__ void gk_compute(const float* __restrict__ wp) {
    int co = blockIdx.x;
    int ci = threadIdx.x;
    const float* p = wp + (co * CIN + ci) * 3;
    float sx = p[0], sy = p[1], th = p[2];
    float rad = th * 0.017453292519943295f;   // th / 180 * pi (matches reference)
    float c = cosf(rad), s = sinf(rad);
    float sx2 = sx * sx, sy2 = sy * sy;
    float a = c * c * sx2 + s * s * sy2;
    float b = c * s * (sx2 - sy2);
    float d = s * s * sx2 + c * c * sy2;
    float det = a * d - b * b;
    float ia = d / det, ib = -b / det, idd = a / det;

    float ker[NTAP];
    float sum = 0.f;
    #pragma unroll
    for (int ky = 0; ky < 9; ky++) {
        float yy = (float)(ky - 4);
        #pragma unroll
        for (int kx = 0; kx < 9; kx++) {
            float xx = (float)(kx - 4);
            float q = ia * xx * xx + 2.0f * ib * xx * yy + idd * yy * yy;
            float v = expf(-0.5f * q);
            ker[ky * 9 + kx] = v;
            sum += v;
        }
    }
    float inv = 1.0f / sum;

    // B[k=ci][n=co] fragment slot: uint4 = {kchunk0 (4 halves), kchunk1 (4 halves)}
    int k     = ci >> 4;            // kchunk
    int kk    = ci & 15;            // row within 16
    int lane4 = (kk & 7) >> 1;      // threadID_in_group
    int sel   = ((kk >> 3) << 1) | (kk & 1);   // half index within kchunk's 4
    int nt    = co >> 3;
    int lane  = ((co & 7) << 2) + lane4;
    size_t hidx = ((size_t)nt * 32 + lane) * 8 + k * 4 + sel;   // half index within tap slab
    __half* wf = (__half*)g_wf;
    #pragma unroll
    for (int t = 0; t < NTAP; t++) {
        wf[(size_t)t * 1024 + hidx] = __float2half_rn(ker[t] * inv);
    }
}

// ---------------------------------------------------------------------------
// Prep 2: NCHW fp32 -> NHWC fp16
// grid (192/32, 192, 16), block (32, 8)
// ---------------------------------------------------------------------------
__global__ void nchw_to_nhwc_h(const float* __restrict__ x) {
    __shared__ float t[32][33];
    const int x0 = blockIdx.x * 32;
    const int y  = blockIdx.y;
    const int n  = blockIdx.z;
    const float* src = x + (size_t)n * CIN * HWP + (size_t)y * WW + x0;
    #pragma unroll
    for (int ci = threadIdx.y; ci < 32; ci += 8)
        t[ci][threadIdx.x] = src[(size_t)ci * HWP + threadIdx.x];
    __syncthreads();
    const int tid = threadIdx.y * 32 + threadIdx.x;
    const int pix = tid >> 3;
    const int cg  = (tid & 7) * 4;
    __half2 h0 = __floats2half2_rn(t[cg + 0][pix], t[cg + 1][pix]);
    __half2 h1 = __floats2half2_rn(t[cg + 2][pix], t[cg + 3][pix]);
    uint2 v;
    v.x = *(uint32_t*)&h0;
    v.y = *(uint32_t*)&h1;
    *(uint2*)(g_xh + ((size_t)n * HWP + (size_t)y * WW + x0 + pix) * 32 + cg) = v;
}

// ---------------------------------------------------------------------------
// helpers
// ---------------------------------------------------------------------------
__device__ __forceinline__ uint32_t smem_u32(const void* p) {
    uint32_t a;
    asm("{ .reg .u64 t; cvta.to.shared.u64 t, %1; cvt.u32.u64 %0, t; }"
        : "=r"(a) : "l"(p));
    return a;
}
__device__ __forceinline__ void cpa16(uint32_t dst, const void* src, int szbytes) {
    asm volatile("cp.async.ca.shared.global [%0], [%1], 16, %2;"
                 :: "r"(dst), "l"(src), "r"(szbytes) : "memory");
}
// f32-accumulate HMMA (k16)
__device__ __forceinline__ void mma16816(float* d,
                                         uint32_t a0, uint32_t a1, uint32_t a2, uint32_t a3,
                                         uint32_t b0, uint32_t b1) {
    asm volatile(
        "mma.sync.aligned.m16n8k16.row.col.f32.f16.f16.f32 "
        "{%0,%1,%2,%3},{%4,%5,%6,%7},{%8,%9},{%0,%1,%2,%3};"
        : "+f"(d[0]), "+f"(d[1]), "+f"(d[2]), "+f"(d[3])
        : "r"(a0), "r"(a1), "r"(a2), "r"(a3), "r"(b0), "r"(b1));
}
// fp16-accumulate HMMA (k16), D/C = 2x f16x2
__device__ __forceinline__ void mma16816h(uint32_t* p,
                                          uint32_t a0, uint32_t a1, uint32_t a2, uint32_t a3,
                                          uint32_t b0, uint32_t b1) {
    asm volatile(
        "mma.sync.aligned.m16n8k16.row.col.f16.f16.f16.f16 "
        "{%0,%1},{%2,%3,%4,%5},{%6,%7},{%0,%1};"
        : "+r"(p[0]), "+r"(p[1])
        : "r"(a0), "r"(a1), "r"(a2), "r"(a3), "r"(b0), "r"(b1));
}
// promote: D32 += P16 x I8  (m16n8k8, fp16 in, f32 acc)
__device__ __forceinline__ void mma1688p(float* d, uint32_t p0, uint32_t p1, uint32_t id) {
    asm volatile(
        "mma.sync.aligned.m16n8k8.row.col.f32.f16.f16.f32 "
        "{%0,%1,%2,%3},{%4,%5},{%6},{%0,%1,%2,%3};"
        : "+f"(d[0]), "+f"(d[1]), "+f"(d[2]), "+f"(d[3])
        : "r"(p0), "r"(p1), "r"(id));
}
__device__ __forceinline__ void ldmat4(uint32_t* r, uint32_t addr) {
    asm volatile("ldmatrix.sync.aligned.m8n8.x4.shared.b16 {%0,%1,%2,%3}, [%4];"
                 : "=r"(r[0]), "=r"(r[1]), "=r"(r[2]), "=r"(r[3]) : "r"(addr));
}

// smem strip geometry: 16 rows x 72 pixels x 64B, 16B-segment swizzled
#define SPXB   64                  // bytes per pixel
#define SPX    72                  // pixels per strip row
#define SROWB  (SPX * SPXB)        // 4608 B per row
#define SSIZE  (16 * SROWB)        // 73728 B
__device__ __forceinline__ uint32_t sw_off(int p, int seg) {
    return (uint32_t)(p * 64 + ((seg ^ ((p >> 1) & 3)) << 4));
}

// ---------------------------------------------------------------------------
// Main: implicit conv. Block = 8 warps, 8 rows x 64 pixels; D[64x32] fp32.
// Taps paired: 4x fp16-acc HMMA chain, promoted via identity k8 HMMA.
// Tail tap (dx=8) on the f32-acc path.
// ---------------------------------------------------------------------------
__global__ __launch_bounds__(256, 2)
void conv_mma(const float* __restrict__ bias, float* __restrict__ out) {
    extern __shared__ __align__(16) char smem[];

    const int tid  = threadIdx.x;
    const int warp = tid >> 5;
    const int lane = tid & 31;
    const int x0 = blockIdx.x * 64;
    const int y0 = blockIdx.y * 8;
    const int n  = blockIdx.z;

    const uint32_t sb = smem_u32(smem);

    // ---- stage 16 rows x 72 px (zfill OOB): 4608 x 16B chunks, 18/thread ----
    {
        const __half* xb = g_xh + (size_t)n * HWP * 32;
        #pragma unroll
        for (int k = 0; k < 18; k++) {
            int i   = tid + k * 256;
            int row = i / 288;
            int rem = i - row * 288;
            int p   = rem >> 2;
            int seg = rem & 3;
            int gy  = y0 - 4 + row;
            int gx  = x0 - 4 + p;
            bool ok = ((unsigned)gy < HH) && ((unsigned)gx < WW);
            const __half* src = ok ? xb + ((size_t)gy * WW + gx) * 32 + seg * 8 : (const __half*)g_xh;
            cpa16(sb + row * SROWB + sw_off(p, seg), src, ok ? 16 : 0);
        }
        asm volatile("cp.async.commit_group;" ::: "memory");
        asm volatile("cp.async.wait_group 0;" ::: "memory");
        __syncthreads();
    }

    // ldmatrix lane geometry (verified R11): pixel offset pl, segment half sh
    const int pl = (lane & 7) + ((lane >> 3) & 1) * 8;
    const int sh = lane >> 4;

    // identity B fragment for the promote HMMA (m16n8k8, row.col):
    // thread holds {I(2*tig, gp), I(2*tig+1, gp)}, tig = lane&3, gp = lane>>2
    uint32_t idreg;
    {
        const int tig = lane & 3, gp = lane >> 2;
        __half2 h = __halves2half2(__float2half(2 * tig == gp ? 1.f : 0.f),
                                   __float2half(2 * tig + 1 == gp ? 1.f : 0.f));
        idreg = *(uint32_t*)&h;
    }

    float d[4][4][4] = {};   // [mtile][ntile][acc]

    #pragma unroll 1
    for (int dy = 0; dy < 9; dy++) {
        const uint32_t rowb = sb + (warp + dy) * SROWB;

        // ---- 4 tap pairs: (0,1)(2,3)(4,5)(6,7), fp16-acc chains ----
        #pragma unroll
        for (int dp = 0; dp < 4; dp++) {
            const int dxa = dp * 2, dxb = dxa + 1;
            const uint4* wfa = g_wf + (dy * 9 + dxa) * 128 + lane;
            const uint4* wfb = g_wf + (dy * 9 + dxb) * 128 + lane;
            uint4 Ba[4], Bb[4];
            #pragma unroll
            for (int nt = 0; nt < 4; nt++) { Ba[nt] = wfa[nt * 32]; Bb[nt] = wfb[nt * 32]; }

            #pragma unroll
            for (int m = 0; m < 4; m++) {
                const int pa = dxa + m * 16 + pl;
                const int pb = dxb + m * 16 + pl;
                uint32_t Aa0[4], Aa1[4], Ab0[4], Ab1[4];
                ldmat4(Aa0, rowb + sw_off(pa, sh));
                ldmat4(Aa1, rowb + sw_off(pa, 2 + sh));
                ldmat4(Ab0, rowb + sw_off(pb, sh));
                ldmat4(Ab1, rowb + sw_off(pb, 2 + sh));
                #pragma unroll
                for (int nt = 0; nt < 4; nt++) {
                    uint32_t P[2] = {0u, 0u};
                    mma16816h(P, Aa0[0], Aa0[1], Aa0[2], Aa0[3], Ba[nt].x, Ba[nt].y);
                    mma16816h(P, Aa1[0], Aa1[1], Aa1[2], Aa1[3], Ba[nt].z, Ba[nt].w);
                    mma16816h(P, Ab0[0], Ab0[1], Ab0[2], Ab0[3], Bb[nt].x, Bb[nt].y);
                    mma16816h(P, Ab1[0], Ab1[1], Ab1[2], Ab1[3], Bb[nt].z, Bb[nt].w);
                    mma1688p(d[m][nt], P[0], P[1], idreg);
                }
            }
        }

        // ---- tail tap dx=8: f32-acc path ----
        {
            const uint4* wf = g_wf + (dy * 9 + 8) * 128 + lane;
            uint4 B[4];
            #pragma unroll
            for (int nt = 0; nt < 4; nt++) B[nt] = wf[nt * 32];
            #pragma unroll
            for (int m = 0; m < 4; m++) {
                const int p = 8 + m * 16 + pl;
                uint32_t A0[4], A1[4];
                ldmat4(A0, rowb + sw_off(p, sh));
                ldmat4(A1, rowb + sw_off(p, 2 + sh));
                #pragma unroll
                for (int nt = 0; nt < 4; nt++) {
                    mma16816(d[m][nt], A0[0], A0[1], A0[2], A0[3], B[nt].x, B[nt].y);
                    mma16816(d[m][nt], A1[0], A1[1], A1[2], A1[3], B[nt].z, B[nt].w);
                }
            }
        }
    }

    // ---- epilogue: D rows = pixels, cols = co ----
    const int g  = lane >> 2;
    const int c0 = (lane & 3) * 2;
    const int y  = y0 + warp;
    float* ob = out + (size_t)n * COUT * HWP + (size_t)y * WW;
    #pragma unroll
    for (int nt = 0; nt < 4; nt++) {
        const int co0 = nt * 8 + c0;
        const float bv0 = bias[co0], bv1 = bias[co0 + 1];
        #pragma unroll
        for (int m = 0; m < 4; m++) {
            const int px = x0 + m * 16 + g;
            ob[(size_t)co0 * HWP + px]           = d[m][nt][0] + bv0;
            ob[(size_t)(co0 + 1) * HWP + px]     = d[m][nt][1] + bv1;
            ob[(size_t)co0 * HWP + px + 8]       = d[m][nt][2] + bv0;
            ob[(size_t)(co0 + 1) * HWP + px + 8] = d[m][nt][3] + bv1;
        }
    }
}

// ---------------------------------------------------------------------------
extern "C" void kernel_launch(void* const* d_in, const int* in_sizes, int n_in,
                              void* d_out, int out_size) {
    const float* x    = (const float*)d_in[0];   // [16, 32, 192, 192]
    const float* wp   = (const float*)d_in[1];   // [32, 32, 3]
    const float* bias = (const float*)d_in[2];   // [32]
    float* out = (float*)d_out;                  // [16, 32, 192, 192]

    cudaFuncSetAttribute(conv_mma, cudaFuncAttributeMaxDynamicSharedMemorySize, SSIZE);

    gk_compute<<<COUT, CIN>>>(wp);
    nchw_to_nhwc_h<<<dim3(WW / 32, HH, NB), dim3(32, 8)>>>(x);
    conv_mma<<<dim3(WW / 64, HH / 8, NB), 256, SSIZE>>>(bias, out);  // 1152 blocks
}

// round 17
// speedup vs baseline: 1.2304x; 1.2304x over previous
#include <cuda_runtime.h>
#include <cuda_fp16.h>
#include <cstdint>

typedef unsigned long long u64;

#define CIN   32
#define COUT  32
#define HH    192
#define WW    192
#define NB    16
#define HWP   (HH * WW)          // 36864
#define NPIX  (NB * HWP)
#define NTAP  81

// NHWC fp16 copy of input: [n][y][x][ci], 64B per pixel
__device__ __align__(16) __half g_xh[(size_t)NPIX * CIN];
// B fragments, packed per ntile: [tap][ntile 4][lane 32] uint4 {B0lo,B0hi,B1lo,B1hi}
__device__ __align__(16) uint4 g_wf[NTAP * 4 * 32];

// ---------------------------------------------------------------------------
// Prep 1: Gaussian kernels -> B fragments (one thread per (co, ci))
// ---------------------------------------------------------------------------
__global__ void gk_compute(const float* __restrict__ wp) {
    int co = blockIdx.x;
    int ci = threadIdx.x;
    const float* p = wp + (co * CIN + ci) * 3;
    float sx = p[0], sy = p[1], th = p[2];
    float rad = th * 0.017453292519943295f;   // th / 180 * pi (matches reference)
    float c = cosf(rad), s = sinf(rad);
    float sx2 = sx * sx, sy2 = sy * sy;
    float a = c * c * sx2 + s * s * sy2;
    float b = c * s * (sx2 - sy2);
    float d = s * s * sx2 + c * c * sy2;
    float det = a * d - b * b;
    float ia = d / det, ib = -b / det, idd = a / det;

    float ker[NTAP];
    float sum = 0.f;
    #pragma unroll
    for (int ky = 0; ky < 9; ky++) {
        float yy = (float)(ky - 4);
        #pragma unroll
        for (int kx = 0; kx < 9; kx++) {
            float xx = (float)(kx - 4);
            float q = ia * xx * xx + 2.0f * ib * xx * yy + idd * yy * yy;
            float v = expf(-0.5f * q);
            ker[ky * 9 + kx] = v;
            sum += v;
        }
    }
    float inv = 1.0f / sum;

    // B[k=ci][n=co] fragment slot: uint4 = {kchunk0 (4 halves), kchunk1 (4 halves)}
    int k     = ci >> 4;            // kchunk
    int kk    = ci & 15;            // row within 16
    int lane4 = (kk & 7) >> 1;      // threadID_in_group
    int sel   = ((kk >> 3) << 1) | (kk & 1);   // half index within kchunk's 4
    int nt    = co >> 3;
    int lane  = ((co & 7) << 2) + lane4;
    size_t hidx = ((size_t)nt * 32 + lane) * 8 + k * 4 + sel;   // half index within tap slab
    __half* wf = (__half*)g_wf;
    #pragma unroll
    for (int t = 0; t < NTAP; t++) {
        wf[(size_t)t * 1024 + hidx] = __float2half_rn(ker[t] * inv);
    }
}

// ---------------------------------------------------------------------------
// Prep 2: NCHW fp32 -> NHWC fp16
// grid (192/32, 192, 16), block (32, 8)
// ---------------------------------------------------------------------------
__global__ void nchw_to_nhwc_h(const float* __restrict__ x) {
    __shared__ float t[32][33];
    const int x0 = blockIdx.x * 32;
    const int y  = blockIdx.y;
    const int n  = blockIdx.z;
    const float* src = x + (size_t)n * CIN * HWP + (size_t)y * WW + x0;
    #pragma unroll
    for (int ci = threadIdx.y; ci < 32; ci += 8)
        t[ci][threadIdx.x] = src[(size_t)ci * HWP + threadIdx.x];
    __syncthreads();
    const int tid = threadIdx.y * 32 + threadIdx.x;
    const int pix = tid >> 3;
    const int cg  = (tid & 7) * 4;
    __half2 h0 = __floats2half2_rn(t[cg + 0][pix], t[cg + 1][pix]);
    __half2 h1 = __floats2half2_rn(t[cg + 2][pix], t[cg + 3][pix]);
    uint2 v;
    v.x = *(uint32_t*)&h0;
    v.y = *(uint32_t*)&h1;
    *(uint2*)(g_xh + ((size_t)n * HWP + (size_t)y * WW + x0 + pix) * 32 + cg) = v;
}

// ---------------------------------------------------------------------------
// helpers
// ---------------------------------------------------------------------------
__device__ __forceinline__ uint32_t smem_u32(const void* p) {
    uint32_t a;
    asm("{ .reg .u64 t; cvta.to.shared.u64 t, %1; cvt.u32.u64 %0, t; }"
        : "=r"(a) : "l"(p));
    return a;
}
__device__ __forceinline__ void cpa16(uint32_t dst, const void* src, int szbytes) {
    asm volatile("cp.async.ca.shared.global [%0], [%1], 16, %2;"
                 :: "r"(dst), "l"(src), "r"(szbytes) : "memory");
}
__device__ __forceinline__ void mma16816(float* d,
                                         uint32_t a0, uint32_t a1, uint32_t a2, uint32_t a3,
                                         uint32_t b0, uint32_t b1) {
    asm volatile(
        "mma.sync.aligned.m16n8k16.row.col.f32.f16.f16.f32 "
        "{%0,%1,%2,%3},{%4,%5,%6,%7},{%8,%9},{%0,%1,%2,%3};"
        : "+f"(d[0]), "+f"(d[1]), "+f"(d[2]), "+f"(d[3])
        : "r"(a0), "r"(a1), "r"(a2), "r"(a3), "r"(b0), "r"(b1));
}
__device__ __forceinline__ void ldmat4(uint32_t* r, uint32_t addr) {
    asm volatile("ldmatrix.sync.aligned.m8n8.x4.shared.b16 {%0,%1,%2,%3}, [%4];"
                 : "=r"(r[0]), "=r"(r[1]), "=r"(r[2]), "=r"(r[3]) : "r"(addr));
}

// smem strip geometry: 24 rows x 72 pixels x 64B, 16B-segment swizzled
#define SPXB   64                  // bytes per pixel
#define SPX    72                  // pixels per strip row
#define SROWB  (SPX * SPXB)        // 4608 B per row
#define SNROW  24                  // strip rows (16 outputs + 8 halo)
#define SSIZE  (SNROW * SROWB)     // 110592 B
__device__ __forceinline__ uint32_t sw_off(int p, int seg) {
    return (uint32_t)(p * 64 + ((seg ^ ((p >> 1) & 3)) << 4));
}

// ---------------------------------------------------------------------------
// Main: implicit conv. Block = 16 warps (512 thr), covers 16 rows x 64 px.
// Warp w = row y0+w, 64 pixels (4 m16 tiles), D[64 x 32co] fp32 in registers.
// Two-phase staging: rows 0-15 by all threads; rows 16-23 by warps 8-15 only
// (writer set == waiter set), so warps 0-7 start compute early.
// ---------------------------------------------------------------------------
__global__ __launch_bounds__(512, 1)
void conv_mma(const float* __restrict__ bias, float* __restrict__ out) {
    extern __shared__ __align__(16) char smem[];

    const int tid  = threadIdx.x;
    const int warp = tid >> 5;
    const int lane = tid & 31;
    const int x0 = blockIdx.x * 64;
    const int y0 = blockIdx.y * 16;
    const int n  = blockIdx.z;

    const uint32_t sb = smem_u32(smem);
    const __half* xb = g_xh + (size_t)n * HWP * 32;

    // chunk -> (row, pixel, seg) and stage via cp.async (zfill OOB)
    auto stage_chunk = [&](int i) {
        int row = i / 288;                 // 288 chunks per strip row
        int rem = i - row * 288;
        int p   = rem >> 2;
        int seg = rem & 3;
        int gy  = y0 - 4 + row;
        int gx  = x0 - 4 + p;
        bool ok = ((unsigned)gy < HH) && ((unsigned)gx < WW);
        const __half* src = ok ? xb + ((size_t)gy * WW + gx) * 32 + seg * 8 : (const __half*)g_xh;
        cpa16(sb + row * SROWB + sw_off(p, seg), src, ok ? 16 : 0);
    };

    // ---- phase 1: rows 0-15 (4608 chunks), all 512 threads, 9 each ----
    #pragma unroll
    for (int k = 0; k < 9; k++) stage_chunk(tid + k * 512);
    asm volatile("cp.async.commit_group;" ::: "memory");

    // ---- phase 2: rows 16-23 (2304 chunks), warps 8-15 only, 9 each ----
    if (tid >= 256) {
        #pragma unroll
        for (int k = 0; k < 9; k++) stage_chunk(4608 + (tid - 256) + k * 256);
        asm volatile("cp.async.commit_group;" ::: "memory");
    }

    // rows 0-15 visible to everyone
    if (tid < 256) { asm volatile("cp.async.wait_group 0;" ::: "memory"); }
    else           { asm volatile("cp.async.wait_group 1;" ::: "memory"); }
    __syncthreads();

    // warps 8-15: rows 16-23 visible among themselves (their own writes)
    if (tid >= 256) {
        asm volatile("cp.async.wait_group 0;" ::: "memory");
        asm volatile("bar.sync 7, 256;" ::: "memory");
    }

    // ldmatrix lane geometry (verified R11): pixel offset pl, segment half sh
    const int pl = (lane & 7) + ((lane >> 3) & 1) * 8;
    const int sh = lane >> 4;

    float d[4][4][4] = {};   // [mtile][ntile][acc]

    #pragma unroll 1
    for (int dy = 0; dy < 9; dy++) {
        const uint32_t rowb = sb + (warp + dy) * SROWB;
        #pragma unroll
        for (int dx = 0; dx < 9; dx++) {
            // B fragments for this tap: 4x LDG.128 (both kchunks packed per ntile)
            const int tap = dy * 9 + dx;
            const uint4* wf = g_wf + tap * 128 + lane;
            uint4 B[4];
            #pragma unroll
            for (int nt = 0; nt < 4; nt++) B[nt] = wf[nt * 32];

            #pragma unroll
            for (int m = 0; m < 4; m++) {
                const int p = dx + m * 16 + pl;
                uint32_t A0[4], A1[4];
                ldmat4(A0, rowb + sw_off(p, sh));        // kchunk 0
                ldmat4(A1, rowb + sw_off(p, 2 + sh));    // kchunk 1
                #pragma unroll
                for (int nt = 0; nt < 4; nt++) {
                    mma16816(d[m][nt], A0[0], A0[1], A0[2], A0[3], B[nt].x, B[nt].y);
                    mma16816(d[m][nt], A1[0], A1[1], A1[2], A1[3], B[nt].z, B[nt].w);
                }
            }
        }
    }

    // ---- epilogue: D rows = pixels, cols = co ----
    const int g  = lane >> 2;
    const int c0 = (lane & 3) * 2;
    const int y  = y0 + warp;
    float* ob = out + (size_t)n * COUT * HWP + (size_t)y * WW;
    #pragma unroll
    for (int nt = 0; nt < 4; nt++) {
        const int co0 = nt * 8 + c0;
        const float bv0 = bias[co0], bv1 = bias[co0 + 1];
        #pragma unroll
        for (int m = 0; m < 4; m++) {
            const int px = x0 + m * 16 + g;
            ob[(size_t)co0 * HWP + px]           = d[m][nt][0] + bv0;
            ob[(size_t)(co0 + 1) * HWP + px]     = d[m][nt][1] + bv1;
            ob[(size_t)co0 * HWP + px + 8]       = d[m][nt][2] + bv0;
            ob[(size_t)(co0 + 1) * HWP + px + 8] = d[m][nt][3] + bv1;
        }
    }
}

// ---------------------------------------------------------------------------
extern "C" void kernel_launch(void* const* d_in, const int* in_sizes, int n_in,
                              void* d_out, int out_size) {
    const float* x    = (const float*)d_in[0];   // [16, 32, 192, 192]
    const float* wp   = (const float*)d_in[1];   // [32, 32, 3]
    const float* bias = (const float*)d_in[2];   // [32]
    float* out = (float*)d_out;                  // [16, 32, 192, 192]

    cudaFuncSetAttribute(conv_mma, cudaFuncAttributeMaxDynamicSharedMemorySize, SSIZE);

    gk_compute<<<COUT, CIN>>>(wp);
    nchw_to_nhwc_h<<<dim3(WW / 32, HH, NB), dim3(32, 8)>>>(x);
    conv_mma<<<dim3(WW / 64, HH / 16, NB), 512, SSIZE>>>(bias, out);  // 576 blocks
}